// round 4
// baseline (speedup 1.0000x reference)
#include <cuda_runtime.h>

// SNN elementwise state update, B*D = 4096*4096 fp32. Pure streaming, HBM-bound.
// Inputs (metadata order): total_input_current, v, x, j, ref_count
// Outputs packed in d_out: [v | s | x | j | ref_count], each B*D floats.
//
// R4: persistent single-wave grid (148 SMs x 8 blocks = 1184 CTAs, 256 thr),
// grid-stride loop. Removes ~13 wave transitions of the 16384-CTA launch;
// each CTA streams ~14 quad-iterations back-to-back so DRAM demand never
// dips at wave boundaries. Body identical to the best-measured R1 kernel.

__device__ __forceinline__ void snn_update(float I, float& v, float& x,
                                           float& j, float& rc, float& s) {
    const float dt       = 0.5f;
    const float dt_tauj  = 0.0625f;   // 0.5/8
    const float kappa_j  = 0.2f;
    const float dt_taum  = 0.05f;     // 0.5/10
    const float gamma_m  = 0.1f;
    const float R_m      = 5.0f;
    const float thresh   = 1.0f;
    const float t_ref    = 2.0f;
    const float inv_ttr  = 0.05f;     // 1/20

    rc = fmaxf(rc - dt, 0.0f);
    j = j + dt_tauj * (-kappa_j * j + I);
    float is_ref = (rc > 0.0f) ? 1.0f : 0.0f;
    v = v + (1.0f - is_ref) * dt_taum * (-gamma_m * v + R_m * j);
    float spikes = (v > thresh) ? 1.0f : 0.0f;
    s = spikes;
    v = v * (1.0f - spikes);
    rc = (spikes > 0.0f) ? t_ref : rc;
    x = x - x * inv_ttr + spikes;
}

__global__ void __launch_bounds__(256)
snn_kernel(const float4* __restrict__ in_I,
           const float4* __restrict__ in_v,
           const float4* __restrict__ in_x,
           const float4* __restrict__ in_j,
           const float4* __restrict__ in_rc,
           float4* __restrict__ out_v,
           float4* __restrict__ out_s,
           float4* __restrict__ out_x,
           float4* __restrict__ out_j,
           float4* __restrict__ out_rc,
           int n4) {
    const int stride = gridDim.x * blockDim.x;
    for (int idx = blockIdx.x * blockDim.x + threadIdx.x; idx < n4; idx += stride) {
        float4 I  = in_I[idx];
        float4 v  = in_v[idx];
        float4 x  = in_x[idx];
        float4 j  = in_j[idx];
        float4 rc = in_rc[idx];
        float4 s;

        snn_update(I.x, v.x, x.x, j.x, rc.x, s.x);
        snn_update(I.y, v.y, x.y, j.y, rc.y, s.y);
        snn_update(I.z, v.z, x.z, j.z, rc.z, s.z);
        snn_update(I.w, v.w, x.w, j.w, rc.w, s.w);

        out_v[idx]  = v;
        out_s[idx]  = s;
        out_x[idx]  = x;
        out_j[idx]  = j;
        out_rc[idx] = rc;
    }
}

extern "C" void kernel_launch(void* const* d_in, const int* in_sizes, int n_in,
                              void* d_out, int out_size) {
    const float4* I  = (const float4*)d_in[0];
    const float4* v  = (const float4*)d_in[1];
    const float4* x  = (const float4*)d_in[2];
    const float4* j  = (const float4*)d_in[3];
    const float4* rc = (const float4*)d_in[4];

    int n  = in_sizes[0];        // B*D elements (16,777,216)
    int n4 = n / 4;              // float4 quads (4,194,304)

    float* out = (float*)d_out;  // [v | s | x | j | ref_count]
    float4* ov  = (float4*)(out + 0L * n);
    float4* os  = (float4*)(out + 1L * n);
    float4* ox  = (float4*)(out + 2L * n);
    float4* oj  = (float4*)(out + 3L * n);
    float4* orc = (float4*)(out + 4L * n);

    // Single wave: 152 SMs on GB300, 8 CTAs/SM at 256 threads (64-warp limit).
    // Use 148*8 = 1184 as the conservative common denominator; a few extra
    // CTAs on a 152-SM part would just make a tiny second wave, so size from
    // the B300 baseline which both parts cover.
    int threads = 256;
    int blocks  = 1184;
    snn_kernel<<<blocks, threads>>>(I, v, x, j, rc, ov, os, ox, oj, orc, n4);
}

// round 5
// speedup vs baseline: 1.1140x; 1.1140x over previous
#include <cuda_runtime.h>

// SNN elementwise state update, B*D = 4096*4096 fp32. Pure streaming, HBM-bound.
// Inputs (metadata order): total_input_current, v, x, j, ref_count
// Outputs packed in d_out: [v | s | x | j | ref_count], each B*D floats.
//
// FINAL (= R1, measured best of 4 structural variants):
//   flat launch, 1 float4 quad per thread, 5 front-batched LDG.128 +
//   5 STG.128, no cache hints, no loops. DRAM busy 83.7%, 6.63 TB/s.
// Variants tested and rejected:
//   R2 2x unroll + __ldcs/__stcs  -> 82.6% (regs 48, occ drop)
//   R3 __stcs stores only          -> 83.1% (neutral)
//   R4 persistent grid-stride      -> 78.1% (loop serializes iteration MLP)
// Binding constraint: HBM read/write-mix bus efficiency — intrinsic.

__device__ __forceinline__ void snn_update(float I, float& v, float& x,
                                           float& j, float& rc, float& s) {
    const float dt       = 0.5f;
    const float dt_tauj  = 0.0625f;   // 0.5/8
    const float kappa_j  = 0.2f;
    const float dt_taum  = 0.05f;     // 0.5/10
    const float gamma_m  = 0.1f;
    const float R_m      = 5.0f;
    const float thresh   = 1.0f;
    const float t_ref    = 2.0f;
    const float inv_ttr  = 0.05f;     // 1/20

    // refractory countdown
    rc = fmaxf(rc - dt, 0.0f);
    // synaptic current leaky integration
    j = j + dt_tauj * (-kappa_j * j + I);
    // membrane update, frozen while refractory
    float is_ref = (rc > 0.0f) ? 1.0f : 0.0f;
    v = v + (1.0f - is_ref) * dt_taum * (-gamma_m * v + R_m * j);
    // threshold -> spike, reset
    float spikes = (v > thresh) ? 1.0f : 0.0f;
    s = spikes;
    v = v * (1.0f - spikes);
    // refractory entry
    rc = (spikes > 0.0f) ? t_ref : rc;
    // low-pass spike trace
    x = x - x * inv_ttr + spikes;
}

__global__ void __launch_bounds__(256)
snn_kernel(const float4* __restrict__ in_I,
           const float4* __restrict__ in_v,
           const float4* __restrict__ in_x,
           const float4* __restrict__ in_j,
           const float4* __restrict__ in_rc,
           float4* __restrict__ out_v,
           float4* __restrict__ out_s,
           float4* __restrict__ out_x,
           float4* __restrict__ out_j,
           float4* __restrict__ out_rc,
           int n4) {
    int idx = blockIdx.x * blockDim.x + threadIdx.x;
    if (idx >= n4) return;

    float4 I  = in_I[idx];
    float4 v  = in_v[idx];
    float4 x  = in_x[idx];
    float4 j  = in_j[idx];
    float4 rc = in_rc[idx];
    float4 s;

    snn_update(I.x, v.x, x.x, j.x, rc.x, s.x);
    snn_update(I.y, v.y, x.y, j.y, rc.y, s.y);
    snn_update(I.z, v.z, x.z, j.z, rc.z, s.z);
    snn_update(I.w, v.w, x.w, j.w, rc.w, s.w);

    out_v[idx]  = v;
    out_s[idx]  = s;
    out_x[idx]  = x;
    out_j[idx]  = j;
    out_rc[idx] = rc;
}

extern "C" void kernel_launch(void* const* d_in, const int* in_sizes, int n_in,
                              void* d_out, int out_size) {
    const float4* I  = (const float4*)d_in[0];
    const float4* v  = (const float4*)d_in[1];
    const float4* x  = (const float4*)d_in[2];
    const float4* j  = (const float4*)d_in[3];
    const float4* rc = (const float4*)d_in[4];

    int n  = in_sizes[0];        // B*D elements (16,777,216)
    int n4 = n / 4;              // float4 quads (4,194,304)

    float* out = (float*)d_out;  // [v | s | x | j | ref_count]
    float4* ov  = (float4*)(out + 0L * n);
    float4* os  = (float4*)(out + 1L * n);
    float4* ox  = (float4*)(out + 2L * n);
    float4* oj  = (float4*)(out + 3L * n);
    float4* orc = (float4*)(out + 4L * n);

    int threads = 256;
    int blocks  = (n4 + threads - 1) / threads;   // 16384
    snn_kernel<<<blocks, threads>>>(I, v, x, j, rc, ov, os, ox, oj, orc, n4);
}

// round 6
// speedup vs baseline: 1.1179x; 1.0035x over previous
#include <cuda_runtime.h>

// SNN elementwise state update, B*D = 4096*4096 fp32. Pure streaming, HBM-bound.
// Inputs (metadata order): total_input_current, v, x, j, ref_count
// Outputs packed in d_out: [v | s | x | j | ref_count], each B*D floats.
//
// R6: R1 body (measured optimum: 1 quad/thread, 5 front-batched LDG.128 +
// 5 STG.128, 32 regs) with the one unsampled knob changed: block 256 -> 512
// (8192 CTAs). Pure CTA-granularity experiment; body byte-identical.
//
// Measured history: R1 83.7% DRAM / 100.5us; R2 unroll+hints 82.6%;
// R3 stcs 83.1%; R4 persistent 78.1%; R5 (=R1) 83.3% / 100.8us.
// Binding constraint: HBM read/write-mix bus efficiency — intrinsic.

__device__ __forceinline__ void snn_update(float I, float& v, float& x,
                                           float& j, float& rc, float& s) {
    const float dt       = 0.5f;
    const float dt_tauj  = 0.0625f;   // 0.5/8
    const float kappa_j  = 0.2f;
    const float dt_taum  = 0.05f;     // 0.5/10
    const float gamma_m  = 0.1f;
    const float R_m      = 5.0f;
    const float thresh   = 1.0f;
    const float t_ref    = 2.0f;
    const float inv_ttr  = 0.05f;     // 1/20

    // refractory countdown
    rc = fmaxf(rc - dt, 0.0f);
    // synaptic current leaky integration
    j = j + dt_tauj * (-kappa_j * j + I);
    // membrane update, frozen while refractory
    float is_ref = (rc > 0.0f) ? 1.0f : 0.0f;
    v = v + (1.0f - is_ref) * dt_taum * (-gamma_m * v + R_m * j);
    // threshold -> spike, reset
    float spikes = (v > thresh) ? 1.0f : 0.0f;
    s = spikes;
    v = v * (1.0f - spikes);
    // refractory entry
    rc = (spikes > 0.0f) ? t_ref : rc;
    // low-pass spike trace
    x = x - x * inv_ttr + spikes;
}

__global__ void __launch_bounds__(512)
snn_kernel(const float4* __restrict__ in_I,
           const float4* __restrict__ in_v,
           const float4* __restrict__ in_x,
           const float4* __restrict__ in_j,
           const float4* __restrict__ in_rc,
           float4* __restrict__ out_v,
           float4* __restrict__ out_s,
           float4* __restrict__ out_x,
           float4* __restrict__ out_j,
           float4* __restrict__ out_rc,
           int n4) {
    int idx = blockIdx.x * blockDim.x + threadIdx.x;
    if (idx >= n4) return;

    float4 I  = in_I[idx];
    float4 v  = in_v[idx];
    float4 x  = in_x[idx];
    float4 j  = in_j[idx];
    float4 rc = in_rc[idx];
    float4 s;

    snn_update(I.x, v.x, x.x, j.x, rc.x, s.x);
    snn_update(I.y, v.y, x.y, j.y, rc.y, s.y);
    snn_update(I.z, v.z, x.z, j.z, rc.z, s.z);
    snn_update(I.w, v.w, x.w, j.w, rc.w, s.w);

    out_v[idx]  = v;
    out_s[idx]  = s;
    out_x[idx]  = x;
    out_j[idx]  = j;
    out_rc[idx] = rc;
}

extern "C" void kernel_launch(void* const* d_in, const int* in_sizes, int n_in,
                              void* d_out, int out_size) {
    const float4* I  = (const float4*)d_in[0];
    const float4* v  = (const float4*)d_in[1];
    const float4* x  = (const float4*)d_in[2];
    const float4* j  = (const float4*)d_in[3];
    const float4* rc = (const float4*)d_in[4];

    int n  = in_sizes[0];        // B*D elements (16,777,216)
    int n4 = n / 4;              // float4 quads (4,194,304)

    float* out = (float*)d_out;  // [v | s | x | j | ref_count]
    float4* ov  = (float4*)(out + 0L * n);
    float4* os  = (float4*)(out + 1L * n);
    float4* ox  = (float4*)(out + 2L * n);
    float4* oj  = (float4*)(out + 3L * n);
    float4* orc = (float4*)(out + 4L * n);

    int threads = 512;
    int blocks  = (n4 + threads - 1) / threads;   // 8192
    snn_kernel<<<blocks, threads>>>(I, v, x, j, rc, ov, os, ox, oj, orc, n4);
}